// round 6
// baseline (speedup 1.0000x reference)
#include <cuda_runtime.h>

// Gray-Scott residual, smem 6-slot plane ring, float2 everywhere, 1 sync/iter.
// Input: output (50,2,100,100,100) fp32. Output: f_u(48,96,96,96) ++ f_v.
//
// Block (16 zp, 16 x) = 256 threads. Tile: 32 out-z (36 in), 16 out-x (20 in),
// marches y 0..95. Ring holds input planes y..y+5 (6 slots); y-taps come from
// smem, not a register ring, keeping regs ~50.

#define TOUT 48
#define D 96
#define IN_T 2000000
#define IN_C 1000000
#define IN_Y 10000
#define IN_X 100
#define N_OUT (TOUT * D * D * D)

#define ZT 32            // out z per block
#define XT 16            // out x per block
#define TXR 20           // input x rows in tile (XT + 4)
#define SW 40            // smem row stride (36 used + pad)
#define PLANE_F 1600     // floats per plane (2ch * 20 * 40)
#define PF2 360          // float2 per channel per plane (20 rows * 18)
#define TOTF2 720        // float2 per plane (both channels)

__device__ __forceinline__ float2 ldg2(const float* p) {
    return __ldg((const float2*)p);
}

__global__ void __launch_bounds__(256, 5) gs6(
    const float* __restrict__ in, float* __restrict__ out)
{
    __shared__ float sm[6][PLANE_F];   // [slot][ch*800? no: ch*?]  flat per plane:
                                       // offset = ch*(TXR*SW) + row*SW + col

    const int tz  = threadIdx.x;       // 0..15 (z pair)
    const int tx  = threadIdx.y;       // 0..15 (out x)
    const int tid = tx * 16 + tz;

    const int z0 = blockIdx.x * ZT;
    const int x0 = blockIdx.y * XT;
    const int t  = blockIdx.z;

    const float* base = in + t * IN_T + x0 * IN_X + z0;

    // ---- loader precompute: 3 strided chunks over 720 float2 ----
    int goff[3], soff[3];
    bool val[3];
    #pragma unroll
    for (int i = 0; i < 3; i++) {
        int flat = tid + 256 * i;
        val[i] = (flat < TOTF2);
        int f = val[i] ? flat : 0;
        int ch = f / PF2;              // 0: u, 1: v
        int q  = f - ch * PF2;
        int row = q / 18, c = q - 18 * row;
        goff[i] = ch * IN_C + row * IN_X + 2 * c;
        soff[i] = ch * (TXR * SW) + row * SW + 2 * c;
    }

    // ---- prologue: planes 0..4 into slots 0..4 ----
    #pragma unroll 1
    for (int p = 0; p < 5; p++) {
        const float* gp = base + p * IN_Y;
        float2 L0, L1, L2;
        if (val[0]) L0 = ldg2(gp + goff[0]);
        if (val[1]) L1 = ldg2(gp + goff[1]);
        if (val[2]) L2 = ldg2(gp + goff[2]);
        if (val[0]) *(float2*)&sm[p][soff[0]] = L0;
        if (val[1]) *(float2*)&sm[p][soff[1]] = L1;
        if (val[2]) *(float2*)&sm[p][soff[2]] = L2;
    }
    __syncthreads();

    const int xc = tx + 2;                      // center row in tile
    const int zc = 2 * tz + 2;                  // center float2 col
    const int uoff = 0;
    const int voff = TXR * SW;

    // t+1 center pointer (u); v = +IN_C
    const float* np0 = in + (t + 1) * IN_T + 2 * IN_Y
                     + (x0 + tx + 2) * IN_X + (z0 + zc);
    float* op0 = out + ((t * D) * D + (x0 + tx)) * D + (z0 + 2 * tz);

    const float INV_DX2 = 2304.0f / 10000.0f;
    const float C1 = 4.0f / 3.0f;
    const float C2 = -1.0f / 12.0f;
    const float C0 = -7.5f;

    int r = 0;                                  // slot of plane y

    #pragma unroll 1
    for (int y = 0; y < D; y++) {
        // ring slots for planes y .. y+5
        int s0 = r;
        int s1 = (s0 == 5) ? 0 : s0 + 1;
        int s2 = (s1 == 5) ? 0 : s1 + 1;
        int s3 = (s2 == 5) ? 0 : s2 + 1;
        int s4 = (s3 == 5) ? 0 : s3 + 1;
        int s5 = (s4 == 5) ? 0 : s4 + 1;        // load target (plane y+5)

        // issue gmem loads for plane y+5 (overlaps compute below)
        float2 L0, L1, L2;
        const bool doload = (y < D - 1);
        if (doload) {
            const float* gp = base + (y + 5) * IN_Y;
            if (val[0]) L0 = ldg2(gp + goff[0]);
            if (val[1]) L1 = ldg2(gp + goff[1]);
            if (val[2]) L2 = ldg2(gp + goff[2]);
        }

        // ---- compute 2 points (z = z0+2tz, z0+2tz+1) ----
        float lap[2][2], cc[2][2], nn[2][2];
        const float* np = np0 + y * IN_Y;

        #pragma unroll
        for (int ch = 0; ch < 2; ch++) {
            const int cb = ch ? voff : uoff;
            const float* pc = &sm[s2][cb + xc * SW];

            float2 w0 = *(const float2*)(pc + 2 * tz);
            float2 w1 = *(const float2*)(pc + zc);
            float2 w2 = *(const float2*)(pc + 2 * tz + 4);

            float2 xm1 = *(const float2*)&sm[s2][cb + (xc - 1) * SW + zc];
            float2 xp1 = *(const float2*)&sm[s2][cb + (xc + 1) * SW + zc];
            float2 xm2 = *(const float2*)&sm[s2][cb + (xc - 2) * SW + zc];
            float2 xp2 = *(const float2*)&sm[s2][cb + (xc + 2) * SW + zc];

            float2 ym2 = *(const float2*)&sm[s0][cb + xc * SW + zc];
            float2 ym1 = *(const float2*)&sm[s1][cb + xc * SW + zc];
            float2 yp1 = *(const float2*)&sm[s3][cb + xc * SW + zc];
            float2 yp2 = *(const float2*)&sm[s4][cb + xc * SW + zc];

            float2 nx = ldg2(np + ch * IN_C);

            // lane 0: z-1=w0.y z+1=w1.y ; z-2=w0.x z+2=w2.x
            float t1_0 = w0.y + w1.y + xm1.x + xp1.x + ym1.x + yp1.x;
            float t2_0 = w0.x + w2.x + xm2.x + xp2.x + ym2.x + yp2.x;
            // lane 1: z-1=w1.x z+1=w2.x ; z-2=w0.y z+2=w2.y
            float t1_1 = w1.x + w2.x + xm1.y + xp1.y + ym1.y + yp1.y;
            float t2_1 = w0.y + w2.y + xm2.y + xp2.y + ym2.y + yp2.y;

            cc[ch][0] = w1.x; cc[ch][1] = w1.y;
            nn[ch][0] = nx.x; nn[ch][1] = nx.y;
            lap[ch][0] = (C0 * w1.x + C1 * t1_0 + C2 * t2_0) * INV_DX2;
            lap[ch][1] = (C0 * w1.y + C1 * t1_1 + C2 * t2_1) * INV_DX2;
        }

        float2 fu, fv;
        {
            float uv2a = cc[0][0] * cc[1][0] * cc[1][0];
            float uv2b = cc[0][1] * cc[1][1] * cc[1][1];
            fu.x = 0.2f * lap[0][0] - uv2a + 0.025f * (1.0f - cc[0][0])
                 - (nn[0][0] - cc[0][0]) * 2.0f;
            fu.y = 0.2f * lap[0][1] - uv2b + 0.025f * (1.0f - cc[0][1])
                 - (nn[0][1] - cc[0][1]) * 2.0f;
            fv.x = 0.1f * lap[1][0] + uv2a - 0.08f * cc[1][0]
                 - (nn[1][0] - cc[1][0]) * 2.0f;
            fv.y = 0.1f * lap[1][1] + uv2b - 0.08f * cc[1][1]
                 - (nn[1][1] - cc[1][1]) * 2.0f;
        }

        float* op = op0 + y * (D * D);
        *(float2*)op           = fu;
        *(float2*)(op + N_OUT) = fv;

        // commit plane y+5 to smem, then one sync
        if (doload) {
            if (val[0]) *(float2*)&sm[s5][soff[0]] = L0;
            if (val[1]) *(float2*)&sm[s5][soff[1]] = L1;
            if (val[2]) *(float2*)&sm[s5][soff[2]] = L2;
        }
        __syncthreads();

        r = s1;
    }
}

extern "C" void kernel_launch(void* const* d_in, const int* in_sizes, int n_in,
                              void* d_out, int out_size)
{
    const float* in = (const float*)d_in[0];
    float* out = (float*)d_out;
    dim3 block(16, 16);                    // 256 threads
    dim3 grid(D / ZT, D / XT, TOUT);       // (3, 6, 48) = 864 blocks
    gs6<<<grid, block>>>(in, out);
}

// round 7
// speedup vs baseline: 1.6629x; 1.6629x over previous
#include <cuda_runtime.h>

// Gray-Scott residual: 2 outputs/thread, float2 loads, z-window via warp shuffle.
// Input: output (50,2,100,100,100) fp32. Output: f_u(48,96,96,96) ++ f_v.

#define TOUT 48
#define D 96
#define IN_T 2000000
#define IN_C 1000000
#define IN_Y 10000
#define IN_X 100
#define N_OUT (TOUT * D * D * D)       // 42467328
#define N_PAIR (N_OUT / 2)             // 21233664

__device__ __forceinline__ float2 ldg2(const float* p) {
    return __ldg((const float2*)p);
}

__device__ __forceinline__ float2 shfl_up2(float2 v) {
    float2 r;
    r.x = __shfl_up_sync(0xffffffffu, v.x, 1);
    r.y = __shfl_up_sync(0xffffffffu, v.y, 1);
    return r;
}
__device__ __forceinline__ float2 shfl_dn2(float2 v) {
    float2 r;
    r.x = __shfl_down_sync(0xffffffffu, v.x, 1);
    r.y = __shfl_down_sync(0xffffffffu, v.y, 1);
    return r;
}

__global__ void __launch_bounds__(256) gs_kernel7(
    const float* __restrict__ in, float* __restrict__ out)
{
    int idx = blockIdx.x * 256 + threadIdx.x;
    if (idx >= N_PAIR) return;

    int zp = idx % (D / 2);            // z pair index: outputs z = 2zp, 2zp+1
    int r  = idx / (D / 2);
    int x  = r % D;
    r /= D;
    int y  = r % D;
    int t  = r / D;

    const int zi = 2 * zp;
    const float* up = in + t * IN_T + (y + 2) * IN_Y + (x + 2) * IN_X + (zi + 2);
    const float* vp = up + IN_C;

    const unsigned lane = threadIdx.x & 31u;

    // centers (z_in zi+2, zi+3)
    float2 uw1 = ldg2(up);
    float2 vw1 = ldg2(vp);

    // z-window edges via neighbor-lane shuffle; fall back to a load where the
    // neighbor lane doesn't exist or belongs to a different x-row.
    const bool haveUp = (lane > 0)  && (zp > 0);
    const bool haveDn = (lane < 31) && (zp < (D / 2 - 1));

    float2 uw0 = shfl_up2(uw1);
    float2 vw0 = shfl_up2(vw1);
    float2 uw2 = shfl_dn2(uw1);
    float2 vw2 = shfl_dn2(vw1);
    if (!haveUp) { uw0 = ldg2(up - 2); vw0 = ldg2(vp - 2); }
    if (!haveDn) { uw2 = ldg2(up + 2); vw2 = ldg2(vp + 2); }

    // x taps
    float2 uxm1 = ldg2(up - IN_X),     uxp1 = ldg2(up + IN_X);
    float2 uxm2 = ldg2(up - 2 * IN_X), uxp2 = ldg2(up + 2 * IN_X);
    float2 vxm1 = ldg2(vp - IN_X),     vxp1 = ldg2(vp + IN_X);
    float2 vxm2 = ldg2(vp - 2 * IN_X), vxp2 = ldg2(vp + 2 * IN_X);

    // y taps
    float2 uym1 = ldg2(up - IN_Y),     uyp1 = ldg2(up + IN_Y);
    float2 uym2 = ldg2(up - 2 * IN_Y), uyp2 = ldg2(up + 2 * IN_Y);
    float2 vym1 = ldg2(vp - IN_Y),     vyp1 = ldg2(vp + IN_Y);
    float2 vym2 = ldg2(vp - 2 * IN_Y), vyp2 = ldg2(vp + 2 * IN_Y);

    // t+1 centers
    float2 un = ldg2(up + IN_T);
    float2 vn = ldg2(vp + IN_T);

    const float INV_DX2 = 2304.0f / 10000.0f;  // 1/DX^2
    const float C1 = 4.0f / 3.0f;
    const float C2 = -1.0f / 12.0f;
    const float C0 = -7.5f;

    float cu0 = uw1.x, cu1 = uw1.y, cv0 = vw1.x, cv1 = vw1.y;

    // lane 0 of pair: z±1 = uw0.y, uw1.y ; z±2 = uw0.x, uw2.x
    // lane 1 of pair: z±1 = uw1.x, uw2.x ; z±2 = uw0.y, uw2.y
    float s1u0 = uw0.y + uw1.y + uxm1.x + uxp1.x + uym1.x + uyp1.x;
    float s2u0 = uw0.x + uw2.x + uxm2.x + uxp2.x + uym2.x + uyp2.x;
    float s1u1 = uw1.x + uw2.x + uxm1.y + uxp1.y + uym1.y + uyp1.y;
    float s2u1 = uw0.y + uw2.y + uxm2.y + uxp2.y + uym2.y + uyp2.y;

    float s1v0 = vw0.y + vw1.y + vxm1.x + vxp1.x + vym1.x + vyp1.x;
    float s2v0 = vw0.x + vw2.x + vxm2.x + vxp2.x + vym2.x + vyp2.x;
    float s1v1 = vw1.x + vw2.x + vxm1.y + vxp1.y + vym1.y + vyp1.y;
    float s2v1 = vw0.y + vw2.y + vxm2.y + vxp2.y + vym2.y + vyp2.y;

    float lapu0 = (C0 * cu0 + C1 * s1u0 + C2 * s2u0) * INV_DX2;
    float lapu1 = (C0 * cu1 + C1 * s1u1 + C2 * s2u1) * INV_DX2;
    float lapv0 = (C0 * cv0 + C1 * s1v0 + C2 * s2v0) * INV_DX2;
    float lapv1 = (C0 * cv1 + C1 * s1v1 + C2 * s2v1) * INV_DX2;

    float uv20 = cu0 * cv0 * cv0;
    float uv21 = cu1 * cv1 * cv1;

    float2 fu, fv;
    fu.x = 0.2f * lapu0 - uv20 + 0.025f * (1.0f - cu0) - (un.x - cu0) * 2.0f;
    fu.y = 0.2f * lapu1 - uv21 + 0.025f * (1.0f - cu1) - (un.y - cu1) * 2.0f;
    fv.x = 0.1f * lapv0 + uv20 - 0.08f * cv0 - (vn.x - cv0) * 2.0f;
    fv.y = 0.1f * lapv1 + uv21 - 0.08f * cv1 - (vn.y - cv1) * 2.0f;

    int oidx = ((t * D + y) * D + x) * D + zi;
    *(float2*)(out + oidx)         = fu;
    *(float2*)(out + oidx + N_OUT) = fv;
}

extern "C" void kernel_launch(void* const* d_in, const int* in_sizes, int n_in,
                              void* d_out, int out_size)
{
    const float* in = (const float*)d_in[0];
    float* out = (float*)d_out;
    int blocks = (N_PAIR + 255) / 256;     // 82944
    gs_kernel7<<<blocks, 256>>>(in, out);
}

// round 8
// speedup vs baseline: 1.8729x; 1.1263x over previous
#include <cuda_runtime.h>

// Gray-Scott residual: 4 outputs/thread (z-pair x y-pair), float2 loads,
// z-window edges via warp shuffle, y-taps shared across the y-pair.
// Input: output (50,2,100,100,100) fp32. Output: f_u(48,96,96,96) ++ f_v.

#define TOUT 48
#define D 96
#define IN_T 2000000
#define IN_C 1000000
#define IN_Y 10000
#define IN_X 100
#define N_OUT (TOUT * D * D * D)       // 42467328
#define NTHREADS (N_OUT / 4)           // 10616832

__device__ __forceinline__ float2 ldg2(const float* p) {
    return __ldg((const float2*)p);
}
__device__ __forceinline__ float2 shfl_up2(float2 v) {
    float2 r;
    r.x = __shfl_up_sync(0xffffffffu, v.x, 1);
    r.y = __shfl_up_sync(0xffffffffu, v.y, 1);
    return r;
}
__device__ __forceinline__ float2 shfl_dn2(float2 v) {
    float2 r;
    r.x = __shfl_down_sync(0xffffffffu, v.x, 1);
    r.y = __shfl_down_sync(0xffffffffu, v.y, 1);
    return r;
}

__global__ void __launch_bounds__(256, 6) gs8(
    const float* __restrict__ in, float* __restrict__ out)
{
    int idx = blockIdx.x * 256 + threadIdx.x;
    if (idx >= NTHREADS) return;

    int zp = idx % (D / 2);            // z pair: outputs z = 2zp, 2zp+1
    int r  = idx / (D / 2);
    int x  = r % D;
    r /= D;
    int y2 = r % (D / 2);              // y pair: outputs y = 2y2, 2y2+1
    int t  = r / (D / 2);
    int y  = 2 * y2;

    const float* P = in + t * IN_T + (y + 2) * IN_Y + (x + 2) * IN_X + (2 * zp + 2);

    const unsigned lane = threadIdx.x & 31u;
    const bool haveUp = (lane > 0)  && (zp > 0);
    const bool haveDn = (lane < 31) && (zp < (D / 2 - 1));

    const float INV_DX2 = 2304.0f / 10000.0f;
    const float C1 = 4.0f / 3.0f;
    const float C2 = -1.0f / 12.0f;
    const float C0 = -7.5f;

    // carried across channel passes: u centers + partial f_u (4 pts)
    float cu0x, cu0y, cu1x, cu1y;
    float pu0x, pu0y, pu1x, pu1y;

    #pragma unroll
    for (int ch = 0; ch < 2; ch++) {
        const float* p = P + ch * IN_C;

        // centers: rows y_in = y+2 (pt row 0) and y+3 (pt row 1)
        float2 c0 = ldg2(p);
        float2 c1 = ldg2(p + IN_Y);

        // z-window edges via shuffle (fallback loads at boundaries)
        float2 w00 = shfl_up2(c0), w20 = shfl_dn2(c0);
        float2 w01 = shfl_up2(c1), w21 = shfl_dn2(c1);
        if (!haveUp) { w00 = ldg2(p - 2); w01 = ldg2(p + IN_Y - 2); }
        if (!haveDn) { w20 = ldg2(p + 2); w21 = ldg2(p + IN_Y + 2); }

        // x-taps, both rows
        float2 xm1_0 = ldg2(p - IN_X),            xp1_0 = ldg2(p + IN_X);
        float2 xm2_0 = ldg2(p - 2 * IN_X),        xp2_0 = ldg2(p + 2 * IN_X);
        float2 xm1_1 = ldg2(p + IN_Y - IN_X),     xp1_1 = ldg2(p + IN_Y + IN_X);
        float2 xm2_1 = ldg2(p + IN_Y - 2 * IN_X), xp2_1 = ldg2(p + IN_Y + 2 * IN_X);

        // shared y-taps: rows y_in = y, y+1, y+4, y+5
        float2 a = ldg2(p - 2 * IN_Y);   // y_in = y
        float2 b = ldg2(p - IN_Y);       // y_in = y+1
        float2 d = ldg2(p + 2 * IN_Y);   // y_in = y+4
        float2 e = ldg2(p + 3 * IN_Y);   // y_in = y+5

        // t+1 centers
        float2 n0 = ldg2(p + IN_T);
        float2 n1 = ldg2(p + IN_T + IN_Y);

        // point row 0 (center c0): ym1=b, ym2=a, yp1=c1, yp2=d
        float s1_0x = w00.y + c0.y + xm1_0.x + xp1_0.x + b.x + c1.x;
        float s2_0x = w00.x + w20.x + xm2_0.x + xp2_0.x + a.x + d.x;
        float s1_0y = c0.x + w20.x + xm1_0.y + xp1_0.y + b.y + c1.y;
        float s2_0y = w00.y + w20.y + xm2_0.y + xp2_0.y + a.y + d.y;
        // point row 1 (center c1): ym1=c0, ym2=b, yp1=d, yp2=e
        float s1_1x = w01.y + c1.y + xm1_1.x + xp1_1.x + c0.x + d.x;
        float s2_1x = w01.x + w21.x + xm2_1.x + xp2_1.x + b.x + e.x;
        float s1_1y = c1.x + w21.x + xm1_1.y + xp1_1.y + c0.y + d.y;
        float s2_1y = w01.y + w21.y + xm2_1.y + xp2_1.y + b.y + e.y;

        float lap0x = (C0 * c0.x + C1 * s1_0x + C2 * s2_0x) * INV_DX2;
        float lap0y = (C0 * c0.y + C1 * s1_0y + C2 * s2_0y) * INV_DX2;
        float lap1x = (C0 * c1.x + C1 * s1_1x + C2 * s2_1x) * INV_DX2;
        float lap1y = (C0 * c1.y + C1 * s1_1y + C2 * s2_1y) * INV_DX2;

        if (ch == 0) {
            // u pass: partial f_u = DU*lap - u_t + FF*(1-u)  (uv2 added later)
            cu0x = c0.x; cu0y = c0.y; cu1x = c1.x; cu1y = c1.y;
            pu0x = 0.2f * lap0x + 0.025f * (1.0f - c0.x) - (n0.x - c0.x) * 2.0f;
            pu0y = 0.2f * lap0y + 0.025f * (1.0f - c0.y) - (n0.y - c0.y) * 2.0f;
            pu1x = 0.2f * lap1x + 0.025f * (1.0f - c1.x) - (n1.x - c1.x) * 2.0f;
            pu1y = 0.2f * lap1y + 0.025f * (1.0f - c1.y) - (n1.y - c1.y) * 2.0f;
        } else {
            // v pass: finalize everything
            float uv0x = cu0x * c0.x * c0.x;
            float uv0y = cu0y * c0.y * c0.y;
            float uv1x = cu1x * c1.x * c1.x;
            float uv1y = cu1y * c1.y * c1.y;

            float2 fu0 = make_float2(pu0x - uv0x, pu0y - uv0y);
            float2 fu1 = make_float2(pu1x - uv1x, pu1y - uv1y);
            float2 fv0, fv1;
            fv0.x = 0.1f * lap0x + uv0x - 0.08f * c0.x - (n0.x - c0.x) * 2.0f;
            fv0.y = 0.1f * lap0y + uv0y - 0.08f * c0.y - (n0.y - c0.y) * 2.0f;
            fv1.x = 0.1f * lap1x + uv1x - 0.08f * c1.x - (n1.x - c1.x) * 2.0f;
            fv1.y = 0.1f * lap1y + uv1y - 0.08f * c1.y - (n1.y - c1.y) * 2.0f;

            int o0 = ((t * D + y) * D + x) * D + 2 * zp;
            int o1 = o0 + D * D;               // y+1 row
            *(float2*)(out + o0)             = fu0;
            *(float2*)(out + o1)             = fu1;
            *(float2*)(out + o0 + N_OUT)     = fv0;
            *(float2*)(out + o1 + N_OUT)     = fv1;
        }
    }
}

extern "C" void kernel_launch(void* const* d_in, const int* in_sizes, int n_in,
                              void* d_out, int out_size)
{
    const float* in = (const float*)d_in[0];
    float* out = (float*)d_out;
    int blocks = (NTHREADS + 255) / 256;   // 41472
    gs8<<<blocks, 256>>>(in, out);
}